// round 2
// baseline (speedup 1.0000x reference)
#include <cuda_runtime.h>
#include <cuda_bf16.h>
#include <math.h>

#define BB 4
#define NN 1024
#define MM 1024
#define DD 1024
#define HH 16
#define HD 64

// Scratch (device globals: no allocation allowed)
__device__ float g_Q[BB * NN * DD];                    // 16 MB   Q[b,n,h*64+d]
__device__ float g_KV[BB * MM * 2 * DD];               // 32 MB   KV[b,m,c,h*64+d]
__device__ float g_Pt[(size_t)BB * HH * NN * MM];      // 268 MB  P_t[b,h,n,m]
__device__ float g_O[BB * NN * DD];                    // 16 MB   O[b,n,h*64+d]
__device__ float g_maskadd[BB * MM];                   // decoded mask additive

#define SCORES_SMEM ((32 * 1024 + 128 * 68 + 32 * 68 + 1024) * 4)
#define TRANS_SMEM (16 * 1025 * 4)

// ---------------------------------------------------------------------------
// Mask decode, dtype-agnostic. Scans first 1024 words: a byte-packed bool
// buffer (4096 bytes) almost surely contains a word >1 that isn't float 1.0;
// int32 0/1 and float32 0.0/1.0 buffers cannot. Then decodes 4096 entries:
//   uint8  -> byte != 0
//   int32/float32 -> word != 0   (0x3F800000 != 0, so both work)
// Single block => flag visible to all decoding threads after __syncthreads.
// ---------------------------------------------------------------------------
__global__ void mask_decode_kernel(const unsigned int* __restrict__ mw) {
    __shared__ int s_u8;
    int tid = threadIdx.x;
    if (tid == 0) s_u8 = 0;
    __syncthreads();
    int u8 = 0;
    for (int i = tid; i < 1024; i += 256) {
        unsigned int w = mw[i];
        if (w > 1u && w != 0x3F800000u) u8 = 1;
    }
    if (u8) atomicOr(&s_u8, 1);
    __syncthreads();
    if (s_u8) {
        const unsigned char* mb = (const unsigned char*)mw;
        for (int i = tid; i < BB * MM; i += 256)
            g_maskadd[i] = mb[i] ? -1e30f : 0.0f;
    } else {
        for (int i = tid; i < BB * MM; i += 256)
            g_maskadd[i] = mw[i] ? -1e30f : 0.0f;
    }
}

// ---------------------------------------------------------------------------
// Generic tiled fp32 GEMM: C[M,N] = A[M,K] @ B[K,N] + bias[N]
// 64x64 block tile, 256 threads, 4x4 per-thread micro-tile, K-chunk 16.
// ---------------------------------------------------------------------------
__global__ void gemm_bias_kernel(const float* __restrict__ A,
                                 const float* __restrict__ B,
                                 const float* __restrict__ bias,
                                 float* __restrict__ C,
                                 int Mdim, int Ndim, int Kdim) {
    __shared__ float As[16][68];
    __shared__ float Bs[16][68];
    int tid = threadIdx.x;
    int tx = tid & 15, ty = tid >> 4;
    int row0 = blockIdx.y * 64;
    int col0 = blockIdx.x * 64;
    float acc[4][4] = {};

    for (int k0 = 0; k0 < Kdim; k0 += 16) {
#pragma unroll
        for (int p = 0; p < 4; p++) {
            int r = (tid >> 4) + p * 16;
            int kk = tid & 15;
            As[kk][r] = A[(size_t)(row0 + r) * Kdim + k0 + kk];
        }
#pragma unroll
        for (int p = 0; p < 4; p++) {
            int kk = (tid >> 6) + p * 4;
            int c = tid & 63;
            Bs[kk][c] = B[(size_t)(k0 + kk) * Ndim + col0 + c];
        }
        __syncthreads();
#pragma unroll
        for (int kk = 0; kk < 16; kk++) {
            float4 a = *(const float4*)&As[kk][ty * 4];
            float4 b = *(const float4*)&Bs[kk][tx * 4];
            acc[0][0] += a.x * b.x; acc[0][1] += a.x * b.y; acc[0][2] += a.x * b.z; acc[0][3] += a.x * b.w;
            acc[1][0] += a.y * b.x; acc[1][1] += a.y * b.y; acc[1][2] += a.y * b.z; acc[1][3] += a.y * b.w;
            acc[2][0] += a.z * b.x; acc[2][1] += a.z * b.y; acc[2][2] += a.z * b.z; acc[2][3] += a.z * b.w;
            acc[3][0] += a.w * b.x; acc[3][1] += a.w * b.y; acc[3][2] += a.w * b.z; acc[3][3] += a.w * b.w;
        }
        __syncthreads();
    }

    float4 bv = *(const float4*)&bias[col0 + tx * 4];
#pragma unroll
    for (int i = 0; i < 4; i++) {
        int r = row0 + ty * 4 + i;
        float4 v = make_float4(acc[i][0] + bv.x, acc[i][1] + bv.y,
                               acc[i][2] + bv.z, acc[i][3] + bv.w);
        *(float4*)&C[(size_t)r * Ndim + col0 + tx * 4] = v;
    }
}

// ---------------------------------------------------------------------------
// Fused scores + mask + softmax per (b, h, 32-row n-tile).
// S tile [32 x 1024] lives in smem; K streamed in 128-row chunks (L2-resident).
// Writes probabilities to g_Pt[b,h,n,m] (fully coalesced).
// ---------------------------------------------------------------------------
__global__ void scores_softmax_kernel() {
    extern __shared__ float smem[];
    float* S = smem;                      // [32][1024]
    float* Ks = S + 32 * 1024;            // [128][68]
    float* Qs = Ks + 128 * 68;            // [32][68]
    float* maskadd = Qs + 32 * 68;        // [1024]

    int tid = threadIdx.x;
    int n0 = blockIdx.x * 32;
    int h = blockIdx.y;
    int b = blockIdx.z;
    const float scale = 0.125f;  // 1/sqrt(64)

    for (int idx = tid; idx < 32 * 64; idx += 256) {
        int i = idx >> 6, d = idx & 63;
        Qs[i * 68 + d] = g_Q[(size_t)(b * NN + n0 + i) * DD + h * HD + d];
    }
    for (int idx = tid; idx < 1024; idx += 256)
        maskadd[idx] = g_maskadd[b * MM + idx];
    __syncthreads();

    int tx = tid & 31, ty = tid >> 5;  // tx -> m quad, ty -> n quad
    for (int m0 = 0; m0 < MM; m0 += 128) {
        for (int idx = tid; idx < 128 * 64; idx += 256) {
            int mr = idx >> 6, d = idx & 63;
            Ks[mr * 68 + d] =
                g_KV[(size_t)(b * MM + m0 + mr) * 2 * DD + h * HD + d];  // keys (c=0)
        }
        __syncthreads();

        float acc[4][4] = {};
#pragma unroll 16
        for (int dd = 0; dd < 64; dd++) {
            float a0 = Qs[(ty * 4 + 0) * 68 + dd];
            float a1 = Qs[(ty * 4 + 1) * 68 + dd];
            float a2 = Qs[(ty * 4 + 2) * 68 + dd];
            float a3 = Qs[(ty * 4 + 3) * 68 + dd];
            float k0 = Ks[(tx * 4 + 0) * 68 + dd];
            float k1 = Ks[(tx * 4 + 1) * 68 + dd];
            float k2 = Ks[(tx * 4 + 2) * 68 + dd];
            float k3 = Ks[(tx * 4 + 3) * 68 + dd];
            acc[0][0] += a0 * k0; acc[0][1] += a0 * k1; acc[0][2] += a0 * k2; acc[0][3] += a0 * k3;
            acc[1][0] += a1 * k0; acc[1][1] += a1 * k1; acc[1][2] += a1 * k2; acc[1][3] += a1 * k3;
            acc[2][0] += a2 * k0; acc[2][1] += a2 * k1; acc[2][2] += a2 * k2; acc[2][3] += a2 * k3;
            acc[3][0] += a3 * k0; acc[3][1] += a3 * k1; acc[3][2] += a3 * k2; acc[3][3] += a3 * k3;
        }

        float m0a = maskadd[m0 + tx * 4 + 0];
        float m1a = maskadd[m0 + tx * 4 + 1];
        float m2a = maskadd[m0 + tx * 4 + 2];
        float m3a = maskadd[m0 + tx * 4 + 3];
#pragma unroll
        for (int i = 0; i < 4; i++) {
            float4 v = make_float4(acc[i][0] * scale + m0a, acc[i][1] * scale + m1a,
                                   acc[i][2] * scale + m2a, acc[i][3] * scale + m3a);
            *(float4*)&S[(ty * 4 + i) * 1024 + m0 + tx * 4] = v;
        }
        __syncthreads();
    }

    // softmax: each warp owns 4 rows
    int lane = tid & 31, w = tid >> 5;
    for (int r = 0; r < 4; r++) {
        float* row = S + (w * 4 + r) * 1024;
        float mx = -1e30f;
        for (int m = lane; m < 1024; m += 32) mx = fmaxf(mx, row[m]);
#pragma unroll
        for (int o = 16; o; o >>= 1) mx = fmaxf(mx, __shfl_xor_sync(0xffffffffu, mx, o));
        float sum = 0.0f;
        for (int m = lane; m < 1024; m += 32) {
            float e = __expf(row[m] - mx);
            row[m] = e;
            sum += e;
        }
#pragma unroll
        for (int o = 16; o; o >>= 1) sum += __shfl_xor_sync(0xffffffffu, sum, o);
        float inv = 1.0f / sum;
        for (int m = lane; m < 1024; m += 32) row[m] *= inv;
    }
    __syncthreads();

    float4* dst = (float4*)&g_Pt[((size_t)(b * HH + h) * NN + n0) * MM];
    const float4* src = (const float4*)S;
    for (int idx = tid; idx < 32 * 1024 / 4; idx += 256) dst[idx] = src[idx];
}

// ---------------------------------------------------------------------------
// O[b,n,h,d] = sum_m P_t[b,h,n,m] * V[b,m,h,d] — tiled GEMM per (b,h).
// ---------------------------------------------------------------------------
__global__ void av_kernel() {
    __shared__ float As[16][68];
    __shared__ float Bs[16][68];
    int tid = threadIdx.x;
    int n0 = blockIdx.x * 64;
    int h = blockIdx.y, b = blockIdx.z;
    int tx = tid & 15, ty = tid >> 4;
    const float* A = g_Pt + ((size_t)(b * HH + h) * NN + n0) * MM;
    float acc[4][4] = {};

    for (int m0 = 0; m0 < MM; m0 += 16) {
#pragma unroll
        for (int p = 0; p < 4; p++) {
            int r = (tid >> 4) + p * 16;
            int kk = tid & 15;
            As[kk][r] = A[(size_t)r * MM + m0 + kk];
        }
#pragma unroll
        for (int p = 0; p < 4; p++) {
            int kk = (tid >> 6) + p * 4;
            int d = tid & 63;
            Bs[kk][d] =
                g_KV[((size_t)(b * MM + m0 + kk) * 2 + 1) * DD + h * HD + d];  // values (c=1)
        }
        __syncthreads();
#pragma unroll
        for (int kk = 0; kk < 16; kk++) {
            float4 a = *(const float4*)&As[kk][ty * 4];
            float4 v = *(const float4*)&Bs[kk][tx * 4];
            acc[0][0] += a.x * v.x; acc[0][1] += a.x * v.y; acc[0][2] += a.x * v.z; acc[0][3] += a.x * v.w;
            acc[1][0] += a.y * v.x; acc[1][1] += a.y * v.y; acc[1][2] += a.y * v.z; acc[1][3] += a.y * v.w;
            acc[2][0] += a.z * v.x; acc[2][1] += a.z * v.y; acc[2][2] += a.z * v.z; acc[2][3] += a.z * v.w;
            acc[3][0] += a.w * v.x; acc[3][1] += a.w * v.y; acc[3][2] += a.w * v.z; acc[3][3] += a.w * v.w;
        }
        __syncthreads();
    }
#pragma unroll
    for (int i = 0; i < 4; i++) {
        float4 v = make_float4(acc[i][0], acc[i][1], acc[i][2], acc[i][3]);
        *(float4*)&g_O[(size_t)(b * NN + n0 + ty * 4 + i) * DD + h * HD + tx * 4] = v;
    }
}

// ---------------------------------------------------------------------------
// P_t[b,h,n,m] -> attn_out[b,n,m,h] (tiled transpose per (b,n))
// ---------------------------------------------------------------------------
__global__ void transpose_kernel(float* __restrict__ attn_out) {
    extern __shared__ float sm[];  // [16][1025]
    int bn = blockIdx.x;
    int b = bn >> 10, n = bn & 1023;
    int tid = threadIdx.x;
    for (int idx = tid; idx < 16 * 1024; idx += 256) {
        int h = idx >> 10, m = idx & 1023;
        sm[h * 1025 + m] = g_Pt[((size_t)(b * HH + h) * NN + n) * MM + m];
    }
    __syncthreads();
    float* dst = attn_out + (size_t)bn * (MM * HH);
    for (int idx = tid; idx < 16 * 1024; idx += 256) {
        int m = idx >> 4, h = idx & 15;
        dst[idx] = sm[h * 1025 + m];
    }
}

// ---------------------------------------------------------------------------
// out[bn, 0:2] = O[bn, :] @ Wp + bp
// ---------------------------------------------------------------------------
__global__ void outproj_kernel(const float* __restrict__ Wp,
                               const float* __restrict__ bp,
                               float* __restrict__ out) {
    int row = blockIdx.x;
    int tid = threadIdx.x;  // 256
    const float4* O4 = (const float4*)(g_O + (size_t)row * DD);
    float4 o = O4[tid];
    const float2* W2 = (const float2*)Wp;
    float2 w0 = W2[tid * 4 + 0];
    float2 w1 = W2[tid * 4 + 1];
    float2 w2 = W2[tid * 4 + 2];
    float2 w3 = W2[tid * 4 + 3];
    float a0 = o.x * w0.x + o.y * w1.x + o.z * w2.x + o.w * w3.x;
    float a1 = o.x * w0.y + o.y * w1.y + o.z * w2.y + o.w * w3.y;
    __shared__ float s0[256], s1[256];
    s0[tid] = a0;
    s1[tid] = a1;
    __syncthreads();
    for (int st = 128; st > 0; st >>= 1) {
        if (tid < st) {
            s0[tid] += s0[tid + st];
            s1[tid] += s1[tid + st];
        }
        __syncthreads();
    }
    if (tid == 0) {
        out[row * 2 + 0] = s0[0] + bp[0];
        out[row * 2 + 1] = s1[0] + bp[1];
    }
}

// ---------------------------------------------------------------------------
extern "C" void kernel_launch(void* const* d_in, const int* in_sizes, int n_in,
                              void* d_out, int out_size) {
    const float* query = (const float*)d_in[0];
    const float* key_value = (const float*)d_in[1];
    const unsigned int* mask_raw = (const unsigned int*)d_in[2];
    const float* Wq = (const float*)d_in[3];
    const float* bq = (const float*)d_in[4];
    const float* Wkv = (const float*)d_in[5];
    const float* bkv = (const float*)d_in[6];
    const float* Wp = (const float*)d_in[7];
    const float* bp = (const float*)d_in[8];

    float* out = (float*)d_out;                 // outputs [4,1024,2]
    float* attn_out = out + BB * NN * 2;        // attention [4,1024,1024,16]

    float *Qp, *KVp;
    cudaGetSymbolAddress((void**)&Qp, g_Q);
    cudaGetSymbolAddress((void**)&KVp, g_KV);

    cudaFuncSetAttribute(scores_softmax_kernel,
                         cudaFuncAttributeMaxDynamicSharedMemorySize, SCORES_SMEM);
    cudaFuncSetAttribute(transpose_kernel,
                         cudaFuncAttributeMaxDynamicSharedMemorySize, TRANS_SMEM);

    // 0) decode mask (dtype-agnostic)
    mask_decode_kernel<<<1, 256>>>(mask_raw);
    // 1) Q = query @ Wq + bq        [4096,1024] x [1024,1024]
    gemm_bias_kernel<<<dim3(DD / 64, BB * NN / 64), 256>>>(query, Wq, bq, Qp,
                                                           BB * NN, DD, DD);
    // 2) KV = key_value @ Wkv + bkv [4096,1024] x [1024,2048]
    gemm_bias_kernel<<<dim3(2 * DD / 64, BB * MM / 64), 256>>>(key_value, Wkv, bkv, KVp,
                                                               BB * MM, 2 * DD, DD);
    // 3) scores + mask + softmax -> g_Pt
    scores_softmax_kernel<<<dim3(NN / 32, HH, BB), 256, SCORES_SMEM>>>();
    // 4) O = P @ V
    av_kernel<<<dim3(NN / 64, HH, BB), 256>>>();
    // 5) attention output (transpose to [b,n,m,h])
    transpose_kernel<<<BB * NN, 256, TRANS_SMEM>>>(attn_out);
    // 6) final projection
    outproj_kernel<<<BB * NN, 256>>>(Wp, bp, out);
}

// round 6
// speedup vs baseline: 2.3407x; 2.3407x over previous
#include <cuda_runtime.h>
#include <cuda_bf16.h>
#include <math.h>
#include <stdint.h>

#define BB 4
#define NN 1024
#define MM 1024
#define DD 1024
#define HH 16
#define HD 64

// ---------------------------------------------------------------------------
// Device scratch (no allocation allowed)
// ---------------------------------------------------------------------------
__device__ float g_Q[BB * NN * DD];                 // Q[b,n,h*64+d]
__device__ float g_KV[BB * MM * 2 * DD];            // KV[b,m,c,h*64+d]
__device__ float g_Pt[(size_t)BB * HH * NN * MM];   // raw masked scores [b,h,n,m]
__device__ float g_O[BB * NN * DD];                 // O[b,n,h*64+d]
__device__ float g_WqT[DD * DD];                    // Wq^T [out,in]
__device__ float g_WkvT[2 * DD * DD];               // Wkv^T [out,in]
__device__ float g_Vt[(size_t)BB * HH * HD * MM];   // V^T [b,h,d,m]
__device__ float g_maskadd[BB * MM];
__device__ float g_mx[BB * HH * NN];
__device__ float g_inv[BB * HH * NN];

#define TRANS_SMEM (16 * 1025 * 4)

// ---------------------------------------------------------------------------
// bf16 split helpers: a = hi + lo (both bf16), products accumulated in f32
// ---------------------------------------------------------------------------
__device__ __forceinline__ void bf16split2(float x, float y, uint32_t& h, uint32_t& l) {
    __nv_bfloat162 hb = __floats2bfloat162_rn(x, y);
    float rx = x - __bfloat162float(hb.x);
    float ry = y - __bfloat162float(hb.y);
    __nv_bfloat162 lb = __floats2bfloat162_rn(rx, ry);
    h = *(uint32_t*)&hb;
    l = *(uint32_t*)&lb;
}

__device__ __forceinline__ void mma_bf16(float* c, const uint32_t* a, const uint32_t* b) {
    asm volatile(
        "mma.sync.aligned.m16n8k16.row.col.f32.bf16.bf16.f32 "
        "{%0,%1,%2,%3}, {%4,%5,%6,%7}, {%8,%9}, {%0,%1,%2,%3};"
        : "+f"(c[0]), "+f"(c[1]), "+f"(c[2]), "+f"(c[3])
        : "r"(a[0]), "r"(a[1]), "r"(a[2]), "r"(a[3]), "r"(b[0]), "r"(b[1]));
}

// ---------------------------------------------------------------------------
// Generic warp-MMA bf16x3 GEMM: C[z][128 x NT] = A @ B^T (+epilogue)
// A: [Mrows, K] K-major (lda). B: [Ncols, K] K-major (ldb).
// MODE 0: += bias[col]   MODE 1: *0.125 + maskadd[b,col]   MODE 2: plain
// ATRANS 1: A elements -> exp(a - mx[row]) * inv[row]   (softmax on the fly)
//
// smem stage layout (u32 units, 20 u32 per 32-element bf16-pair row):
//   sAh[128*20] | sAl[128*20] | sBh[NT*20] | sBl[NT*20]     x2 stages
// ---------------------------------------------------------------------------
template <int NT, int MODE, int ATRANS>
__global__ void __launch_bounds__(256, 1)
gemm_mma_kernel(const float* __restrict__ A, const float* __restrict__ B,
                const float* __restrict__ bias, float* __restrict__ C,
                long lda, long ldb, long ldc, int Kdim,
                long aB, long aH, long bB, long bH, long cB, long cH, int HHdiv) {
    constexpr int WC = NT / 32;        // warp cols (4 or 2)
    constexpr int WR = 8 / WC;         // warp rows (2 or 4)
    constexpr int MW = 128 / WR;       // m per warp (64 or 32)
    constexpr int MT = MW / 16;        // m-tiles per warp (4 or 2)
    constexpr int NB = NT / 32;        // B float4s per thread per stage
    constexpr int AOFF = 0;
    constexpr int ALOFF = 128 * 20;
    constexpr int BOFF = 2 * 128 * 20;
    constexpr int BLOFF = BOFF + NT * 20;
    constexpr int STAGE = BLOFF + NT * 20;

    extern __shared__ uint32_t smem_u[];
    __shared__ float s_mx[128], s_inv[128];

    int tid = threadIdx.x, wid = tid >> 5, lane = tid & 31;
    int z = blockIdx.z;
    int b = z / HHdiv, h = z % HHdiv;
    int row0 = blockIdx.x * 128, col0 = blockIdx.y * NT;
    int wc = wid % WC, wr = wid / WC;
    int g = lane >> 2, t = lane & 3;

    if (ATRANS) {
        for (int i = tid; i < 128; i += 256) {
            s_mx[i] = g_mx[(size_t)z * NN + row0 + i];
            s_inv[i] = g_inv[(size_t)z * NN + row0 + i];
        }
        __syncthreads();
    }

    const float* Abase = A + (size_t)b * aB + (size_t)h * aH + (size_t)row0 * lda;
    const float* Bbase = B + (size_t)b * bB + (size_t)h * bH + (size_t)col0 * ldb;

    int ra = tid >> 3, c4 = tid & 7;   // A/B loader coords (row, float4-in-row)

    // ---- prefetch + store helpers (inline lambdas via macros) ----
    float4 pA[4], pB[NB];
#define PREFETCH(k0)                                                            \
    do {                                                                        \
        _Pragma("unroll") for (int i = 0; i < 4; i++)                           \
            pA[i] = *(const float4*)(Abase + (size_t)(ra + i * 32) * lda + (k0) + c4 * 4); \
        _Pragma("unroll") for (int i = 0; i < NB; i++)                          \
            pB[i] = *(const float4*)(Bbase + (size_t)(ra + i * 32) * ldb + (k0) + c4 * 4); \
    } while (0)

#define STORE_STAGE(buf)                                                        \
    do {                                                                        \
        uint32_t* st = smem_u + (buf) * STAGE;                                  \
        _Pragma("unroll") for (int i = 0; i < 4; i++) {                         \
            float4 v = pA[i];                                                   \
            int r = ra + i * 32;                                                \
            if (ATRANS) {                                                       \
                float m = s_mx[r], iv = s_inv[r];                               \
                v.x = __expf(v.x - m) * iv; v.y = __expf(v.y - m) * iv;         \
                v.z = __expf(v.z - m) * iv; v.w = __expf(v.w - m) * iv;         \
            }                                                                   \
            uint32_t h0, l0, h1, l1;                                            \
            bf16split2(v.x, v.y, h0, l0);                                       \
            bf16split2(v.z, v.w, h1, l1);                                       \
            st[AOFF + r * 20 + c4 * 2] = h0;  st[AOFF + r * 20 + c4 * 2 + 1] = h1; \
            st[ALOFF + r * 20 + c4 * 2] = l0; st[ALOFF + r * 20 + c4 * 2 + 1] = l1; \
        }                                                                       \
        _Pragma("unroll") for (int i = 0; i < NB; i++) {                        \
            float4 v = pB[i];                                                   \
            int r = ra + i * 32;                                                \
            uint32_t h0, l0, h1, l1;                                            \
            bf16split2(v.x, v.y, h0, l0);                                       \
            bf16split2(v.z, v.w, h1, l1);                                       \
            st[BOFF + r * 20 + c4 * 2] = h0;  st[BOFF + r * 20 + c4 * 2 + 1] = h1; \
            st[BLOFF + r * 20 + c4 * 2] = l0; st[BLOFF + r * 20 + c4 * 2 + 1] = l1; \
        }                                                                       \
    } while (0)

    float acc[MT][4][4] = {};

    PREFETCH(0);
    STORE_STAGE(0);
    __syncthreads();

    int KT = Kdim >> 5;
    for (int kt = 0; kt < KT; kt++) {
        int cur = kt & 1;
        if (kt + 1 < KT) PREFETCH((kt + 1) << 5);

        const uint32_t* st = smem_u + cur * STAGE;
#pragma unroll
        for (int kk = 0; kk < 2; kk++) {
            uint32_t bh[4][2], bl[4][2];
#pragma unroll
            for (int ni = 0; ni < 4; ni++) {
                int n = wc * 32 + ni * 8 + g;
                const uint32_t* pbh = st + BOFF + n * 20 + kk * 8 + t;
                const uint32_t* pbl = st + BLOFF + n * 20 + kk * 8 + t;
                bh[ni][0] = pbh[0]; bh[ni][1] = pbh[4];
                bl[ni][0] = pbl[0]; bl[ni][1] = pbl[4];
            }
#pragma unroll
            for (int mi = 0; mi < MT; mi++) {
                int r = wr * MW + mi * 16 + g;
                int base = r * 20 + kk * 8 + t;
                uint32_t ah[4], al[4];
                ah[0] = st[AOFF + base];           ah[2] = st[AOFF + base + 4];
                ah[1] = st[AOFF + base + 8 * 20];  ah[3] = st[AOFF + base + 8 * 20 + 4];
                al[0] = st[ALOFF + base];          al[2] = st[ALOFF + base + 4];
                al[1] = st[ALOFF + base + 8 * 20]; al[3] = st[ALOFF + base + 8 * 20 + 4];
#pragma unroll
                for (int ni = 0; ni < 4; ni++) {
                    mma_bf16(acc[mi][ni], ah, bh[ni]);
                    mma_bf16(acc[mi][ni], ah, bl[ni]);
                    mma_bf16(acc[mi][ni], al, bh[ni]);
                }
            }
        }

        if (kt + 1 < KT) STORE_STAGE(cur ^ 1);
        __syncthreads();
    }
#undef PREFETCH
#undef STORE_STAGE

    // ---- epilogue ----
    float* Cz = C + (size_t)b * cB + (size_t)h * cH;
#pragma unroll
    for (int mi = 0; mi < MT; mi++) {
#pragma unroll
        for (int ni = 0; ni < 4; ni++) {
            int row = row0 + wr * MW + mi * 16 + g;
            int col = col0 + wc * 32 + ni * 8 + 2 * t;
            float2 v0 = make_float2(acc[mi][ni][0], acc[mi][ni][1]);
            float2 v1 = make_float2(acc[mi][ni][2], acc[mi][ni][3]);
            if (MODE == 0) {
                float2 bb = *(const float2*)(bias + col);
                v0.x += bb.x; v0.y += bb.y; v1.x += bb.x; v1.y += bb.y;
            } else if (MODE == 1) {
                float2 mk = *(const float2*)(g_maskadd + (size_t)b * MM + col);
                v0.x = v0.x * 0.125f + mk.x; v0.y = v0.y * 0.125f + mk.y;
                v1.x = v1.x * 0.125f + mk.x; v1.y = v1.y * 0.125f + mk.y;
            }
            *(float2*)(Cz + (size_t)row * ldc + col) = v0;
            *(float2*)(Cz + (size_t)(row + 8) * ldc + col) = v1;
        }
    }
}

// ---------------------------------------------------------------------------
// Mask decode (dtype-agnostic, verified R2)
// ---------------------------------------------------------------------------
__global__ void mask_decode_kernel(const unsigned int* __restrict__ mw) {
    __shared__ int s_u8;
    int tid = threadIdx.x;
    if (tid == 0) s_u8 = 0;
    __syncthreads();
    int u8 = 0;
    for (int i = tid; i < 1024; i += 256) {
        unsigned int w = mw[i];
        if (w > 1u && w != 0x3F800000u) u8 = 1;
    }
    if (u8) atomicOr(&s_u8, 1);
    __syncthreads();
    if (s_u8) {
        const unsigned char* mb = (const unsigned char*)mw;
        for (int i = tid; i < BB * MM; i += 256) g_maskadd[i] = mb[i] ? -1e30f : 0.0f;
    } else {
        for (int i = tid; i < BB * MM; i += 256) g_maskadd[i] = mw[i] ? -1e30f : 0.0f;
    }
}

// ---------------------------------------------------------------------------
// Weight transpose: dst[c][r] = src[r][c]
// ---------------------------------------------------------------------------
__global__ void transposeW_kernel(const float* __restrict__ src, float* __restrict__ dst,
                                  int rows, int cols) {
    __shared__ float tbuf[32][33];
    int c0 = blockIdx.x * 32, r0 = blockIdx.y * 32;
    int tx = threadIdx.x, ty = threadIdx.y;
    for (int i = ty; i < 32; i += 8) tbuf[i][tx] = src[(size_t)(r0 + i) * cols + c0 + tx];
    __syncthreads();
    for (int i = ty; i < 32; i += 8) dst[(size_t)(c0 + i) * rows + r0 + tx] = tbuf[tx][i];
}

// V^T: g_Vt[b,h,d,m] = g_KV[b,m,1,h,d]
__global__ void transposeV_kernel() {
    __shared__ float tbuf[32][33];
    int m0 = blockIdx.x * 32, d0 = blockIdx.y * 32, z = blockIdx.z;
    int b = z >> 4, h = z & 15;
    int tx = threadIdx.x, ty = threadIdx.y;
    for (int i = ty; i < 32; i += 8)
        tbuf[i][tx] = g_KV[((size_t)(b * MM + m0 + i) * 2 + 1) * DD + h * HD + d0 + tx];
    __syncthreads();
    for (int i = ty; i < 32; i += 8)
        g_Vt[((size_t)z * HD + d0 + i) * MM + m0 + tx] = tbuf[tx][i];
}

// ---------------------------------------------------------------------------
// Row stats: max + 1/sum(exp) per (b,h,n) row of raw scores
// ---------------------------------------------------------------------------
__global__ void rowstats_kernel() {
    int row = blockIdx.x * 8 + (threadIdx.x >> 5);
    int lane = threadIdx.x & 31;
    const float* S = g_Pt + (size_t)row * MM;
    float v[32];
    float mx = -1e30f;
#pragma unroll
    for (int j = 0; j < 32; j++) {
        v[j] = S[j * 32 + lane];
        mx = fmaxf(mx, v[j]);
    }
#pragma unroll
    for (int o = 16; o; o >>= 1) mx = fmaxf(mx, __shfl_xor_sync(0xffffffffu, mx, o));
    float sum = 0.0f;
#pragma unroll
    for (int j = 0; j < 32; j++) sum += __expf(v[j] - mx);
#pragma unroll
    for (int o = 16; o; o >>= 1) sum += __shfl_xor_sync(0xffffffffu, sum, o);
    if (lane == 0) {
        g_mx[row] = mx;
        g_inv[row] = 1.0f / sum;
    }
}

// ---------------------------------------------------------------------------
// attention output: softmax applied on the fly + transpose to [b,n,m,h]
// ---------------------------------------------------------------------------
__global__ void transpose_softmax_kernel(float* __restrict__ attn_out) {
    extern __shared__ float sm[];  // [16][1025]
    __shared__ float smx[16], sinv[16];
    int bn = blockIdx.x;
    int b = bn >> 10, n = bn & 1023;
    int tid = threadIdx.x;
    if (tid < 16) {
        smx[tid] = g_mx[(size_t)(b * HH + tid) * NN + n];
        sinv[tid] = g_inv[(size_t)(b * HH + tid) * NN + n];
    }
    __syncthreads();
    for (int idx = tid; idx < 16 * 1024; idx += 256) {
        int h = idx >> 10, m = idx & 1023;
        float s = g_Pt[((size_t)(b * HH + h) * NN + n) * MM + m];
        sm[h * 1025 + m] = __expf(s - smx[h]) * sinv[h];
    }
    __syncthreads();
    float* dst = attn_out + (size_t)bn * (MM * HH);
    for (int idx = tid; idx < 16 * 1024; idx += 256) {
        int m = idx >> 4, h = idx & 15;
        dst[idx] = sm[h * 1025 + m];
    }
}

// ---------------------------------------------------------------------------
// out[bn, 0:2] = O[bn, :] @ Wp + bp
// ---------------------------------------------------------------------------
__global__ void outproj_kernel(const float* __restrict__ Wp, const float* __restrict__ bp,
                               float* __restrict__ out) {
    int row = blockIdx.x;
    int tid = threadIdx.x;
    const float4* O4 = (const float4*)(g_O + (size_t)row * DD);
    float4 o = O4[tid];
    const float2* W2 = (const float2*)Wp;
    float2 w0 = W2[tid * 4 + 0];
    float2 w1 = W2[tid * 4 + 1];
    float2 w2 = W2[tid * 4 + 2];
    float2 w3 = W2[tid * 4 + 3];
    float a0 = o.x * w0.x + o.y * w1.x + o.z * w2.x + o.w * w3.x;
    float a1 = o.x * w0.y + o.y * w1.y + o.z * w2.y + o.w * w3.y;
    __shared__ float s0[256], s1[256];
    s0[tid] = a0;
    s1[tid] = a1;
    __syncthreads();
    for (int st = 128; st > 0; st >>= 1) {
        if (tid < st) {
            s0[tid] += s0[tid + st];
            s1[tid] += s1[tid + st];
        }
        __syncthreads();
    }
    if (tid == 0) {
        out[row * 2 + 0] = s0[0] + bp[0];
        out[row * 2 + 1] = s1[0] + bp[1];
    }
}

// ---------------------------------------------------------------------------
extern "C" void kernel_launch(void* const* d_in, const int* in_sizes, int n_in,
                              void* d_out, int out_size) {
    const float* query = (const float*)d_in[0];
    const float* key_value = (const float*)d_in[1];
    const unsigned int* mask_raw = (const unsigned int*)d_in[2];
    const float* Wq = (const float*)d_in[3];
    const float* bq = (const float*)d_in[4];
    const float* Wkv = (const float*)d_in[5];
    const float* bkv = (const float*)d_in[6];
    const float* Wp = (const float*)d_in[7];
    const float* bp = (const float*)d_in[8];

    float* out = (float*)d_out;           // outputs [4,1024,2]
    float* attn_out = out + BB * NN * 2;  // attention [4,1024,1024,16]

    float *Qp, *KVp, *WqTp, *WkvTp, *Vtp, *Ptp, *Op;
    cudaGetSymbolAddress((void**)&Qp, g_Q);
    cudaGetSymbolAddress((void**)&KVp, g_KV);
    cudaGetSymbolAddress((void**)&WqTp, g_WqT);
    cudaGetSymbolAddress((void**)&WkvTp, g_WkvT);
    cudaGetSymbolAddress((void**)&Vtp, g_Vt);
    cudaGetSymbolAddress((void**)&Ptp, g_Pt);
    cudaGetSymbolAddress((void**)&Op, g_O);

    // dynamic smem: 2 stages of (2*128 + 2*NT) rows * 80 bytes
    const int DYN128 = 2 * ((2 * 128 + 2 * 128) * 80);  // 81920
    const int DYN64 = 2 * ((2 * 128 + 2 * 64) * 80);    // 61440
    cudaFuncSetAttribute(gemm_mma_kernel<128, 0, 0>, cudaFuncAttributeMaxDynamicSharedMemorySize, DYN128);
    cudaFuncSetAttribute(gemm_mma_kernel<128, 1, 0>, cudaFuncAttributeMaxDynamicSharedMemorySize, DYN128);
    cudaFuncSetAttribute(gemm_mma_kernel<64, 2, 1>, cudaFuncAttributeMaxDynamicSharedMemorySize, DYN64);
    cudaFuncSetAttribute(transpose_softmax_kernel, cudaFuncAttributeMaxDynamicSharedMemorySize, TRANS_SMEM);

    // 0) mask decode + weight transposes
    mask_decode_kernel<<<1, 256>>>(mask_raw);
    transposeW_kernel<<<dim3(DD / 32, DD / 32), dim3(32, 8)>>>(Wq, WqTp, DD, DD);
    transposeW_kernel<<<dim3(2 * DD / 32, DD / 32), dim3(32, 8)>>>(Wkv, WkvTp, DD, 2 * DD);

    // 1) Q = query @ Wq + bq
    gemm_mma_kernel<128, 0, 0><<<dim3(BB * NN / 128, DD / 128, 1), 256, DYN128>>>(
        query, WqTp, bq, Qp, DD, DD, DD, DD, 0, 0, 0, 0, 0, 0, 1);
    // 2) KV = key_value @ Wkv + bkv
    gemm_mma_kernel<128, 0, 0><<<dim3(BB * MM / 128, 2 * DD / 128, 1), 256, DYN128>>>(
        key_value, WkvTp, bkv, KVp, DD, DD, 2 * DD, DD, 0, 0, 0, 0, 0, 0, 1);
    // 3) V^T (needs KV)
    transposeV_kernel<<<dim3(MM / 32, HD / 32, BB * HH), dim3(32, 8)>>>();
    // 4) raw masked scores: g_Pt[b,h,n,m] = 0.125*(Q K^T) + maskadd
    gemm_mma_kernel<128, 1, 0><<<dim3(NN / 128, MM / 128, BB * HH), 256, DYN128>>>(
        Qp, KVp, nullptr, Ptp,
        DD, 2 * DD, MM, HD,
        (long)NN * DD, HD, (long)MM * 2 * DD, HD,
        (long)HH * NN * MM, (long)NN * MM, HH);
    // 5) row stats
    rowstats_kernel<<<BB * HH * NN / 8, 256>>>();
    // 6) O = softmax(S) @ V  (softmax applied in A-loader)
    gemm_mma_kernel<64, 2, 1><<<dim3(NN / 128, 1, BB * HH), 256, DYN64>>>(
        Ptp, Vtp, nullptr, Op,
        MM, MM, DD, MM,
        (long)HH * NN * MM, (long)NN * MM, (long)HH * HD * MM, (long)HD * MM,
        (long)NN * DD, HD, HH);
    // 7) attention output (softmax + transpose to [b,n,m,h])
    transpose_softmax_kernel<<<BB * NN, 256, TRANS_SMEM>>>(attn_out);
    // 8) final projection
    outproj_kernel<<<BB * NN, 256>>>(Wp, bp, out);
}